// round 5
// baseline (speedup 1.0000x reference)
#include <cuda_runtime.h>
#include <math.h>
#include <stdint.h>
#include <mma.h>

using namespace nvcuda;

#define TT    1024
#define DIM   512
#define NG    8
#define NE    8
#define NPAIR 64
#define HDIM  1024

__device__ int   d_cnt[NPAIR];
__device__ int   d_tok[NPAIR][TT];
__device__ int   d_asg[NPAIR][TT];
__device__ float d_w[TT * 4];
__device__ float d_H[TT * 4][HDIM];
__device__ float d_Y[TT * 4][DIM];

// round-to-nearest tf32 conversion (unbiased, matches __float_to_tf32)
__device__ __forceinline__ float tf32r(float v) {
    uint32_t r;
    asm("cvt.rna.tf32.f32 %0, %1;" : "=r"(r) : "f"(v));
    return __uint_as_float(r);
}

// ---------------- kernel 0: reset pair counters ----------------
__global__ void zero_cnt_kernel() {
    if (threadIdx.x < NPAIR) d_cnt[threadIdx.x] = 0;
}

// ---------------- kernel 1: routing (one warp per token) ----------------
__global__ void route_kernel(const float* __restrict__ x,
                             const float* __restrict__ g1,
                             const float* __restrict__ g2) {
    int t = (blockIdx.x * blockDim.x + threadIdx.x) >> 5;
    int lane = threadIdx.x & 31;
    if (t >= TT) return;
    const float* xt = x + (size_t)t * DIM;

    float a[NG];
#pragma unroll
    for (int g = 0; g < NG; g++) a[g] = 0.f;
    for (int i = lane; i < DIM; i += 32) {
        float xv = xt[i];
        const float* gp = g1 + (size_t)i * NG;
#pragma unroll
        for (int g = 0; g < NG; g++) a[g] += xv * gp[g];
    }
#pragma unroll
    for (int off = 16; off; off >>= 1)
#pragma unroll
        for (int g = 0; g < NG; g++) a[g] += __shfl_xor_sync(0xffffffffu, a[g], off);

    int i1 = 0; float v1 = a[0];
#pragma unroll
    for (int g = 1; g < NG; g++) if (a[g] > v1) { v1 = a[g]; i1 = g; }
    int i2 = -1; float v2 = -1e30f;
#pragma unroll
    for (int g = 0; g < NG; g++) if (g != i1 && a[g] > v2) { v2 = a[g]; i2 = g; }
    float e2 = expf(v2 - v1);
    float inv = 1.f / (1.f + e2);
    int   gs[2]  = { i1, i2 };
    float c1w[2] = { inv, e2 * inv };

    float b[2 * NE];
#pragma unroll
    for (int q = 0; q < 2 * NE; q++) b[q] = 0.f;
    const float* p0base = g2 + (size_t)gs[0] * DIM * NE;
    const float* p1base = g2 + (size_t)gs[1] * DIM * NE;
    for (int i = lane; i < DIM; i += 32) {
        float xv = xt[i];
        const float* p0 = p0base + (size_t)i * NE;
        const float* p1 = p1base + (size_t)i * NE;
#pragma unroll
        for (int e = 0; e < NE; e++) { b[e] += xv * p0[e]; b[NE + e] += xv * p1[e]; }
    }
#pragma unroll
    for (int off = 16; off; off >>= 1)
#pragma unroll
        for (int q = 0; q < 2 * NE; q++) b[q] += __shfl_xor_sync(0xffffffffu, b[q], off);

    if (lane == 0) {
#pragma unroll
        for (int r = 0; r < 2; r++) {
            int j1 = 0; float u1 = b[r * NE + 0];
#pragma unroll
            for (int e = 1; e < NE; e++) if (b[r * NE + e] > u1) { u1 = b[r * NE + e]; j1 = e; }
            int j2 = -1; float u2 = -1e30f;
#pragma unroll
            for (int e = 0; e < NE; e++) if (e != j1 && b[r * NE + e] > u2) { u2 = b[r * NE + e]; j2 = e; }
            float f2   = expf(u2 - u1);
            float inv2 = 1.f / (1.f + f2);
            int   pe[2]  = { j1, j2 };
            float c2w[2] = { inv2, f2 * inv2 };
            int g = gs[r];
#pragma unroll
            for (int rr = 0; rr < 2; rr++) {
                int pair = g * NE + pe[rr];
                int slot = r * 2 + rr;
                int pos  = atomicAdd(&d_cnt[pair], 1);
                d_tok[pair][pos] = t;
                d_asg[pair][pos] = t * 4 + slot;
                d_w[t * 4 + slot] = c1w[r] * c2w[rr];
            }
        }
    }
}

// ---------------- WMMA tf32 grouped GEMM ----------------
// Per CTA: (pair, 128-col n-tile). BM=64, BN=128, BK=16. 8 warps in 2x4 grid,
// warp tile 32x32 via m16n16k8 tf32 wmma. Register prefetch of next k-chunk.
template <int K, int NTOT, bool RELU, bool LAYER2>
__global__ __launch_bounds__(256) void moe_gemm_wmma(const float* __restrict__ Xg,
                                                     const float* __restrict__ Wt,
                                                     const float* __restrict__ bias) {
    constexpr int BM = 64, BN = 128, BK = 16;
    const int pair  = blockIdx.y;
    const int count = d_cnt[pair];
    if (count == 0) return;
    const int n0 = blockIdx.x * BN;

    const float* Xsrc = LAYER2 ? &d_H[0][0] : Xg;
    float*       Out  = LAYER2 ? &d_Y[0][0] : &d_H[0][0];
    const int*   rows = LAYER2 ? d_asg[pair] : d_tok[pair];
    const float* Wp   = Wt + (size_t)pair * K * NTOT + n0;
    const float* bp   = bias + (size_t)pair * NTOT + n0;

    __shared__ __align__(16) float As[BM][BK];       // 4 KB  (m x k, tf32 bits)
    __shared__ __align__(16) float Bs[BK][BN];       // 8 KB  (k x n, tf32 bits)
    __shared__ __align__(16) float Cs[BM][BN];       // 32 KB (epilogue)
    __shared__ float bsm[BN];
    __shared__ const float* rp[BM];

    const int tid = threadIdx.x;
    const int wid = tid >> 5;
    const int wm = wid >> 2;          // 0..1
    const int wn = wid & 3;           // 0..3

    if (tid < BN) bsm[tid] = bp[tid];

    // A-staging coords: one float4 per thread
    const int am = tid >> 2;          // 0..63
    const int ak = (tid & 3) * 4;     // 0,4,8,12
    // B-staging coords: two float4 per thread
    const int br = tid >> 5;          // 0..7 (and +8)
    const int bc = (tid & 31) * 4;    // 0..124

    for (int m0 = 0; m0 < count; m0 += BM) {
        if (tid < BM) {
            int m = m0 + tid;
            rp[tid] = (m < count) ? (Xsrc + (size_t)rows[m] * K) : (const float*)0;
        }
        __syncthreads();

        wmma::fragment<wmma::accumulator, 16, 16, 8, float> acc[2][2];
#pragma unroll
        for (int i = 0; i < 2; i++)
#pragma unroll
            for (int j = 0; j < 2; j++) wmma::fill_fragment(acc[i][j], 0.f);

        // prefetch chunk 0
        const float* arow = rp[am];
        float4 pa = make_float4(0.f, 0.f, 0.f, 0.f);
        if (arow) pa = *reinterpret_cast<const float4*>(arow + ak);
        float4 pb0 = *reinterpret_cast<const float4*>(Wp + (size_t)br * NTOT + bc);
        float4 pb1 = *reinterpret_cast<const float4*>(Wp + (size_t)(br + 8) * NTOT + bc);

        for (int k0 = 0; k0 < K; k0 += BK) {
            // commit prefetched chunk (tf32-rounded)
            As[am][ak + 0] = tf32r(pa.x); As[am][ak + 1] = tf32r(pa.y);
            As[am][ak + 2] = tf32r(pa.z); As[am][ak + 3] = tf32r(pa.w);
            Bs[br][bc + 0] = tf32r(pb0.x); Bs[br][bc + 1] = tf32r(pb0.y);
            Bs[br][bc + 2] = tf32r(pb0.z); Bs[br][bc + 3] = tf32r(pb0.w);
            Bs[br + 8][bc + 0] = tf32r(pb1.x); Bs[br + 8][bc + 1] = tf32r(pb1.y);
            Bs[br + 8][bc + 2] = tf32r(pb1.z); Bs[br + 8][bc + 3] = tf32r(pb1.w);
            __syncthreads();

            // prefetch next chunk while tensor cores work
            if (k0 + BK < K) {
                const int kn = k0 + BK;
                pa = make_float4(0.f, 0.f, 0.f, 0.f);
                if (arow) pa = *reinterpret_cast<const float4*>(arow + kn + ak);
                pb0 = *reinterpret_cast<const float4*>(Wp + (size_t)(kn + br) * NTOT + bc);
                pb1 = *reinterpret_cast<const float4*>(Wp + (size_t)(kn + br + 8) * NTOT + bc);
            }

#pragma unroll
            for (int kk = 0; kk < BK; kk += 8) {
                wmma::fragment<wmma::matrix_a, 16, 16, 8, wmma::precision::tf32, wmma::row_major> af[2];
                wmma::fragment<wmma::matrix_b, 16, 16, 8, wmma::precision::tf32, wmma::row_major> bf[2];
#pragma unroll
                for (int i = 0; i < 2; i++)
                    wmma::load_matrix_sync(af[i], &As[wm * 32 + i * 16][kk], BK);
#pragma unroll
                for (int j = 0; j < 2; j++)
                    wmma::load_matrix_sync(bf[j], &Bs[kk][wn * 32 + j * 16], BN);
#pragma unroll
                for (int i = 0; i < 2; i++)
#pragma unroll
                    for (int j = 0; j < 2; j++)
                        wmma::mma_sync(acc[i][j], af[i], bf[j], acc[i][j]);
            }
            __syncthreads();
        }

        // epilogue: accum -> Cs -> bias(+relu) -> scatter
#pragma unroll
        for (int i = 0; i < 2; i++)
#pragma unroll
            for (int j = 0; j < 2; j++)
                wmma::store_matrix_sync(&Cs[wm * 32 + i * 16][wn * 32 + j * 16],
                                        acc[i][j], BN, wmma::mem_row_major);
        __syncthreads();

#pragma unroll
        for (int it = 0; it < 8; it++) {
            int c = tid + it * 256;          // float4 index, 0..2047
            int row = c >> 5;                // 32 float4 per row
            int col = (c & 31) * 4;
            int m = m0 + row;
            if (m < count) {
                int asg = d_asg[pair][m];
                float4 v = *reinterpret_cast<const float4*>(&Cs[row][col]);
                v.x += bsm[col + 0]; v.y += bsm[col + 1];
                v.z += bsm[col + 2]; v.w += bsm[col + 3];
                if (RELU) {
                    v.x = fmaxf(v.x, 0.f); v.y = fmaxf(v.y, 0.f);
                    v.z = fmaxf(v.z, 0.f); v.w = fmaxf(v.w, 0.f);
                }
                *reinterpret_cast<float4*>(Out + (size_t)asg * NTOT + n0 + col) = v;
            }
        }
        __syncthreads();
    }
}

// ---------------- kernel 4: weighted combine ----------------
__global__ void combine_kernel(float* __restrict__ out) {
    int t = blockIdx.x;
    float w0 = d_w[t * 4 + 0], w1 = d_w[t * 4 + 1];
    float w2 = d_w[t * 4 + 2], w3 = d_w[t * 4 + 3];
    for (int i = threadIdx.x; i < DIM; i += blockDim.x) {
        float s = w0 * d_Y[t * 4 + 0][i] + w1 * d_Y[t * 4 + 1][i]
                + w2 * d_Y[t * 4 + 2][i] + w3 * d_Y[t * 4 + 3][i];
        out[(size_t)t * DIM + i] = s;
    }
}

// ---------------- launch ----------------
extern "C" void kernel_launch(void* const* d_in, const int* in_sizes, int n_in,
                              void* d_out, int out_size) {
    const float* x  = (const float*)d_in[0];
    const float* g1 = (const float*)d_in[1];
    const float* g2 = (const float*)d_in[2];
    const float* W1 = (const float*)d_in[3];
    const float* b1 = (const float*)d_in[4];
    const float* W2 = (const float*)d_in[5];
    const float* b2 = (const float*)d_in[6];
    float* out = (float*)d_out;

    zero_cnt_kernel<<<1, 64>>>();
    route_kernel<<<(TT * 32) / 128, 128>>>(x, g1, g2);
    // layer 1: [count,512] @ [512,1024] + b1, relu  -> d_H
    moe_gemm_wmma<DIM, HDIM, true,  false><<<dim3(HDIM / 128, NPAIR), 256>>>(x, W1, b1);
    // layer 2: [count,1024] @ [1024,512] + b2       -> d_Y
    moe_gemm_wmma<HDIM, DIM, false, true ><<<dim3(DIM / 128, NPAIR), 256>>>(x, W2, b2);
    combine_kernel<<<TT, 128>>>(out);
}

// round 6
// speedup vs baseline: 1.2531x; 1.2531x over previous
#include <cuda_runtime.h>
#include <math.h>
#include <stdint.h>
#include <mma.h>

using namespace nvcuda;

#define TT    1024
#define DIM   512
#define NG    8
#define NE    8
#define NPAIR 64
#define HDIM  1024

__device__ int   d_cnt[NPAIR];
__device__ int   d_tok[NPAIR][TT];
__device__ int   d_asg[NPAIR][TT];
__device__ float d_w[TT * 4];
__device__ float d_H[TT * 4][HDIM];
__device__ float d_Y[TT * 4][DIM];

// round-to-nearest tf32 conversion (unbiased)
__device__ __forceinline__ float tf32r(float v) {
    uint32_t r;
    asm("cvt.rna.tf32.f32 %0, %1;" : "=r"(r) : "f"(v));
    return __uint_as_float(r);
}

// ---------------- kernel 0: reset pair counters ----------------
__global__ void zero_cnt_kernel() {
    if (threadIdx.x < NPAIR) d_cnt[threadIdx.x] = 0;
}

// ---------------- kernel 1: routing (one warp per token) ----------------
__global__ void route_kernel(const float* __restrict__ x,
                             const float* __restrict__ g1,
                             const float* __restrict__ g2) {
    int t = (blockIdx.x * blockDim.x + threadIdx.x) >> 5;
    int lane = threadIdx.x & 31;
    if (t >= TT) return;
    const float* xt = x + (size_t)t * DIM;

    float a[NG];
#pragma unroll
    for (int g = 0; g < NG; g++) a[g] = 0.f;
    for (int i = lane; i < DIM; i += 32) {
        float xv = xt[i];
        const float* gp = g1 + (size_t)i * NG;
#pragma unroll
        for (int g = 0; g < NG; g++) a[g] += xv * gp[g];
    }
#pragma unroll
    for (int off = 16; off; off >>= 1)
#pragma unroll
        for (int g = 0; g < NG; g++) a[g] += __shfl_xor_sync(0xffffffffu, a[g], off);

    int i1 = 0; float v1 = a[0];
#pragma unroll
    for (int g = 1; g < NG; g++) if (a[g] > v1) { v1 = a[g]; i1 = g; }
    int i2 = -1; float v2 = -1e30f;
#pragma unroll
    for (int g = 0; g < NG; g++) if (g != i1 && a[g] > v2) { v2 = a[g]; i2 = g; }
    float e2 = expf(v2 - v1);
    float inv = 1.f / (1.f + e2);
    int   gs[2]  = { i1, i2 };
    float c1w[2] = { inv, e2 * inv };

    float b[2 * NE];
#pragma unroll
    for (int q = 0; q < 2 * NE; q++) b[q] = 0.f;
    const float* p0base = g2 + (size_t)gs[0] * DIM * NE;
    const float* p1base = g2 + (size_t)gs[1] * DIM * NE;
    for (int i = lane; i < DIM; i += 32) {
        float xv = xt[i];
        const float* p0 = p0base + (size_t)i * NE;
        const float* p1 = p1base + (size_t)i * NE;
#pragma unroll
        for (int e = 0; e < NE; e++) { b[e] += xv * p0[e]; b[NE + e] += xv * p1[e]; }
    }
#pragma unroll
    for (int off = 16; off; off >>= 1)
#pragma unroll
        for (int q = 0; q < 2 * NE; q++) b[q] += __shfl_xor_sync(0xffffffffu, b[q], off);

    if (lane == 0) {
#pragma unroll
        for (int r = 0; r < 2; r++) {
            int j1 = 0; float u1 = b[r * NE + 0];
#pragma unroll
            for (int e = 1; e < NE; e++) if (b[r * NE + e] > u1) { u1 = b[r * NE + e]; j1 = e; }
            int j2 = -1; float u2 = -1e30f;
#pragma unroll
            for (int e = 0; e < NE; e++) if (e != j1 && b[r * NE + e] > u2) { u2 = b[r * NE + e]; j2 = e; }
            float f2   = expf(u2 - u1);
            float inv2 = 1.f / (1.f + f2);
            int   pe[2]  = { j1, j2 };
            float c2w[2] = { inv2, f2 * inv2 };
            int g = gs[r];
#pragma unroll
            for (int rr = 0; rr < 2; rr++) {
                int pair = g * NE + pe[rr];
                int slot = r * 2 + rr;
                int pos  = atomicAdd(&d_cnt[pair], 1);
                d_tok[pair][pos] = t;
                d_asg[pair][pos] = t * 4 + slot;
                d_w[t * 4 + slot] = c1w[r] * c2w[rr];
            }
        }
    }
}

// ---------------- WMMA tf32 grouped GEMM, double-buffered ----------------
// Per CTA: (pair, 64-col n-tile). BM=64, BN=64, BK=32. 128 threads = 4 warps
// in 2x2 grid, warp tile 32x32 (m16n16k8 tf32). One __syncthreads per k-stage;
// STS of stage c+1 overlaps MMA of stage c. Epilogue reuses stage smem.
template <int K, int NTOT, bool RELU, bool LAYER2>
__global__ __launch_bounds__(128, 4) void moe_gemm_wmma(const float* __restrict__ Xg,
                                                        const float* __restrict__ Wt,
                                                        const float* __restrict__ bias) {
    constexpr int BM = 64, BN = 64, BK = 32, NKC = K / BK;
    constexpr int LDA = 36, LDB = 68, LDC = 68;
    const int pair  = blockIdx.y;
    const int count = d_cnt[pair];
    if (count == 0) return;
    const int n0 = blockIdx.x * BN;

    const float* Xsrc = LAYER2 ? &d_H[0][0] : Xg;
    float*       Out  = LAYER2 ? &d_Y[0][0] : &d_H[0][0];
    const int*   rows = LAYER2 ? d_asg[pair] : d_tok[pair];
    const float* Wp   = Wt + (size_t)pair * K * NTOT + n0;
    const float* bp   = bias + (size_t)pair * NTOT + n0;

    // flat pool: [As0 | Bs0 | As1 | Bs1], epilogue Cs aliases the front
    __shared__ __align__(16) float pool[2 * (BM * LDA + BK * LDB)];
    __shared__ float bsm[BN];
    __shared__ const float* rp[BM];
    __shared__ int atb[BM];
    float* const AsB[2] = { pool, pool + BM * LDA + BK * LDB };
    float* const BsB[2] = { pool + BM * LDA, pool + 2 * BM * LDA + BK * LDB };
    float* const Cs = pool;

    const int tid = threadIdx.x;
    const int wid = tid >> 5;
    const int wm = wid >> 1;          // 0..1
    const int wn = wid & 1;           // 0..1

    if (tid < BN) bsm[tid] = bp[tid];

    // staging coords (4 float4 each for A and B)
    int arow[4], akc[4], brow[4], bcol[4];
#pragma unroll
    for (int i = 0; i < 4; i++) {
        int f = tid + i * 128;
        arow[i] = f >> 3; akc[i] = (f & 7) * 4;      // A: 8 float4 per 32-k row
        brow[i] = f >> 4; bcol[i] = (f & 15) * 4;    // B: 16 float4 per 64-n row
    }

    for (int m0 = 0; m0 < count; m0 += BM) {
        if (tid < BM) {
            int m = m0 + tid;
            rp[tid]  = (m < count) ? (Xsrc + (size_t)rows[m] * K) : (const float*)0;
            atb[tid] = (m < count) ? d_asg[pair][m] : 0;
        }
        __syncthreads();

        const float* myrow[4];
#pragma unroll
        for (int i = 0; i < 4; i++) myrow[i] = rp[arow[i]];

        wmma::fragment<wmma::accumulator, 16, 16, 8, float> acc[2][2];
#pragma unroll
        for (int i = 0; i < 2; i++)
#pragma unroll
            for (int j = 0; j < 2; j++) wmma::fill_fragment(acc[i][j], 0.f);

        float4 pa[4], pb[4];
        // prefetch + commit stage 0
#pragma unroll
        for (int i = 0; i < 4; i++) {
            pa[i] = make_float4(0.f, 0.f, 0.f, 0.f);
            if (myrow[i]) pa[i] = *reinterpret_cast<const float4*>(myrow[i] + akc[i]);
            pb[i] = *reinterpret_cast<const float4*>(Wp + (size_t)brow[i] * NTOT + bcol[i]);
        }
#pragma unroll
        for (int i = 0; i < 4; i++) {
            float* a = AsB[0] + arow[i] * LDA + akc[i];
            a[0] = tf32r(pa[i].x); a[1] = tf32r(pa[i].y); a[2] = tf32r(pa[i].z); a[3] = tf32r(pa[i].w);
            float* b = BsB[0] + brow[i] * LDB + bcol[i];
            b[0] = tf32r(pb[i].x); b[1] = tf32r(pb[i].y); b[2] = tf32r(pb[i].z); b[3] = tf32r(pb[i].w);
        }
        __syncthreads();

        for (int c = 0; c < NKC; c++) {
            if (c + 1 < NKC) {
                const int kn = (c + 1) * BK;
#pragma unroll
                for (int i = 0; i < 4; i++) {
                    pa[i] = make_float4(0.f, 0.f, 0.f, 0.f);
                    if (myrow[i]) pa[i] = *reinterpret_cast<const float4*>(myrow[i] + kn + akc[i]);
                    pb[i] = *reinterpret_cast<const float4*>(Wp + (size_t)(kn + brow[i]) * NTOT + bcol[i]);
                }
            }

            const float* Asc = AsB[c & 1];
            const float* Bsc = BsB[c & 1];
#pragma unroll
            for (int kk = 0; kk < BK; kk += 8) {
                wmma::fragment<wmma::matrix_a, 16, 16, 8, wmma::precision::tf32, wmma::row_major> af[2];
                wmma::fragment<wmma::matrix_b, 16, 16, 8, wmma::precision::tf32, wmma::row_major> bf[2];
#pragma unroll
                for (int i = 0; i < 2; i++)
                    wmma::load_matrix_sync(af[i], Asc + (wm * 32 + i * 16) * LDA + kk, LDA);
#pragma unroll
                for (int j = 0; j < 2; j++)
                    wmma::load_matrix_sync(bf[j], Bsc + kk * LDB + wn * 32 + j * 16, LDB);
#pragma unroll
                for (int i = 0; i < 2; i++)
#pragma unroll
                    for (int j = 0; j < 2; j++)
                        wmma::mma_sync(acc[i][j], af[i], bf[j], acc[i][j]);
            }

            if (c + 1 < NKC) {
                float* An = AsB[(c + 1) & 1];
                float* Bn = BsB[(c + 1) & 1];
#pragma unroll
                for (int i = 0; i < 4; i++) {
                    float* a = An + arow[i] * LDA + akc[i];
                    a[0] = tf32r(pa[i].x); a[1] = tf32r(pa[i].y); a[2] = tf32r(pa[i].z); a[3] = tf32r(pa[i].w);
                    float* b = Bn + brow[i] * LDB + bcol[i];
                    b[0] = tf32r(pb[i].x); b[1] = tf32r(pb[i].y); b[2] = tf32r(pb[i].z); b[3] = tf32r(pb[i].w);
                }
                __syncthreads();
            }
        }

        // epilogue: all MMAs done -> reuse pool as Cs
        __syncthreads();
#pragma unroll
        for (int i = 0; i < 2; i++)
#pragma unroll
            for (int j = 0; j < 2; j++)
                wmma::store_matrix_sync(Cs + (wm * 32 + i * 16) * LDC + wn * 32 + j * 16,
                                        acc[i][j], LDC, wmma::mem_row_major);
        __syncthreads();

#pragma unroll
        for (int it = 0; it < 8; it++) {
            int f = tid + it * 128;            // float4 index over 64x64
            int row = f >> 4;
            int col = (f & 15) * 4;
            int m = m0 + row;
            if (m < count) {
                const float* cr = Cs + row * LDC + col;
                float4 v = make_float4(cr[0], cr[1], cr[2], cr[3]);
                v.x += bsm[col + 0]; v.y += bsm[col + 1];
                v.z += bsm[col + 2]; v.w += bsm[col + 3];
                if (RELU) {
                    v.x = fmaxf(v.x, 0.f); v.y = fmaxf(v.y, 0.f);
                    v.z = fmaxf(v.z, 0.f); v.w = fmaxf(v.w, 0.f);
                }
                *reinterpret_cast<float4*>(Out + (size_t)atb[row] * NTOT + n0 + col) = v;
            }
        }
        __syncthreads();
    }
}

// ---------------- kernel 4: weighted combine ----------------
__global__ void combine_kernel(float* __restrict__ out) {
    int t = blockIdx.x;
    float w0 = d_w[t * 4 + 0], w1 = d_w[t * 4 + 1];
    float w2 = d_w[t * 4 + 2], w3 = d_w[t * 4 + 3];
    for (int i = threadIdx.x; i < DIM; i += blockDim.x) {
        float s = w0 * d_Y[t * 4 + 0][i] + w1 * d_Y[t * 4 + 1][i]
                + w2 * d_Y[t * 4 + 2][i] + w3 * d_Y[t * 4 + 3][i];
        out[(size_t)t * DIM + i] = s;
    }
}

// ---------------- launch ----------------
extern "C" void kernel_launch(void* const* d_in, const int* in_sizes, int n_in,
                              void* d_out, int out_size) {
    const float* x  = (const float*)d_in[0];
    const float* g1 = (const float*)d_in[1];
    const float* g2 = (const float*)d_in[2];
    const float* W1 = (const float*)d_in[3];
    const float* b1 = (const float*)d_in[4];
    const float* W2 = (const float*)d_in[5];
    const float* b2 = (const float*)d_in[6];
    float* out = (float*)d_out;

    zero_cnt_kernel<<<1, 64>>>();
    route_kernel<<<(TT * 32) / 128, 128>>>(x, g1, g2);
    // layer 1: [count,512] @ [512,1024] + b1, relu  -> d_H
    moe_gemm_wmma<DIM, HDIM, true,  false><<<dim3(HDIM / 64, NPAIR), 128>>>(x, W1, b1);
    // layer 2: [count,1024] @ [1024,512] + b2       -> d_Y
    moe_gemm_wmma<HDIM, DIM, false, true ><<<dim3(DIM / 64, NPAIR), 128>>>(x, W2, b2);
    combine_kernel<<<TT, 128>>>(out);
}

// round 8
// speedup vs baseline: 1.4728x; 1.1753x over previous
#include <cuda_runtime.h>
#include <math.h>
#include <stdint.h>
#include <mma.h>

using namespace nvcuda;

#define TT    1024
#define DIM   512
#define NG    8
#define NE    8
#define NPAIR 64
#define HDIM  1024

__device__ int   d_cnt[NPAIR];
__device__ int   d_tok[NPAIR][TT];
__device__ int   d_asg[NPAIR][TT];
__device__ float d_w[TT * 4];
__device__ float d_H[TT * 4][HDIM];
__device__ float d_Y[TT * 4][DIM];

// round-to-nearest tf32 conversion (unbiased)
__device__ __forceinline__ float tf32r(float v) {
    uint32_t r;
    asm("cvt.rna.tf32.f32 %0, %1;" : "=r"(r) : "f"(v));
    return __uint_as_float(r);
}
__device__ __forceinline__ uint32_t smem_u32(const void* p) {
    uint32_t a;
    asm("{ .reg .u64 t; cvta.to.shared.u64 t, %1; cvt.u32.u64 %0, t; }" : "=r"(a) : "l"(p));
    return a;
}
__device__ __forceinline__ void cp16(uint32_t s, const void* g) {
    asm volatile("cp.async.cg.shared.global [%0], [%1], 16;" :: "r"(s), "l"(g));
}
#define CP_COMMIT() asm volatile("cp.async.commit_group;" ::: "memory")
#define CP_WAIT1()  asm volatile("cp.async.wait_group 1;" ::: "memory")
#define CP_WAIT0()  asm volatile("cp.async.wait_group 0;" ::: "memory")

// B enters the MMA as raw fp32 bits (HW tf32 truncation, bias -2^-11 per operand):
// correct the systematic scale in the epilogue.
#define CORR 1.00048828125f

// ---------------- kernel 0: reset pair counters ----------------
__global__ void zero_cnt_kernel() {
    if (threadIdx.x < NPAIR) d_cnt[threadIdx.x] = 0;
}

// ---------------- kernel 1: routing (one warp per token) ----------------
__global__ void route_kernel(const float* __restrict__ x,
                             const float* __restrict__ g1,
                             const float* __restrict__ g2) {
    int t = (blockIdx.x * blockDim.x + threadIdx.x) >> 5;
    int lane = threadIdx.x & 31;
    if (t >= TT) return;
    const float* xt = x + (size_t)t * DIM;

    float a[NG];
#pragma unroll
    for (int g = 0; g < NG; g++) a[g] = 0.f;
    for (int i = lane; i < DIM; i += 32) {
        float xv = xt[i];
        const float* gp = g1 + (size_t)i * NG;
#pragma unroll
        for (int g = 0; g < NG; g++) a[g] += xv * gp[g];
    }
#pragma unroll
    for (int off = 16; off; off >>= 1)
#pragma unroll
        for (int g = 0; g < NG; g++) a[g] += __shfl_xor_sync(0xffffffffu, a[g], off);

    int i1 = 0; float v1 = a[0];
#pragma unroll
    for (int g = 1; g < NG; g++) if (a[g] > v1) { v1 = a[g]; i1 = g; }
    int i2 = -1; float v2 = -1e30f;
#pragma unroll
    for (int g = 0; g < NG; g++) if (g != i1 && a[g] > v2) { v2 = a[g]; i2 = g; }
    float e2 = expf(v2 - v1);
    float inv = 1.f / (1.f + e2);
    int   gs[2]  = { i1, i2 };
    float c1w[2] = { inv, e2 * inv };

    float b[2 * NE];
#pragma unroll
    for (int q = 0; q < 2 * NE; q++) b[q] = 0.f;
    const float* p0base = g2 + (size_t)gs[0] * DIM * NE;
    const float* p1base = g2 + (size_t)gs[1] * DIM * NE;
    for (int i = lane; i < DIM; i += 32) {
        float xv = xt[i];
        const float* p0 = p0base + (size_t)i * NE;
        const float* p1 = p1base + (size_t)i * NE;
#pragma unroll
        for (int e = 0; e < NE; e++) { b[e] += xv * p0[e]; b[NE + e] += xv * p1[e]; }
    }
#pragma unroll
    for (int off = 16; off; off >>= 1)
#pragma unroll
        for (int q = 0; q < 2 * NE; q++) b[q] += __shfl_xor_sync(0xffffffffu, b[q], off);

    if (lane == 0) {
#pragma unroll
        for (int r = 0; r < 2; r++) {
            int j1 = 0; float u1 = b[r * NE + 0];
#pragma unroll
            for (int e = 1; e < NE; e++) if (b[r * NE + e] > u1) { u1 = b[r * NE + e]; j1 = e; }
            int j2 = -1; float u2 = -1e30f;
#pragma unroll
            for (int e = 0; e < NE; e++) if (e != j1 && b[r * NE + e] > u2) { u2 = b[r * NE + e]; j2 = e; }
            float f2   = expf(u2 - u1);
            float inv2 = 1.f / (1.f + f2);
            int   pe[2]  = { j1, j2 };
            float c2w[2] = { inv2, f2 * inv2 };
            int g = gs[r];
#pragma unroll
            for (int rr = 0; rr < 2; rr++) {
                int pair = g * NE + pe[rr];
                int slot = r * 2 + rr;
                int pos  = atomicAdd(&d_cnt[pair], 1);
                d_tok[pair][pos] = t;
                d_asg[pair][pos] = t * 4 + slot;
                d_w[t * 4 + slot] = c1w[r] * c2w[rr];
            }
        }
    }
}

// ---------------- WMMA tf32 grouped GEMM: cp.async B pipeline ----------------
// Per CTA: (pair, 128-col n-tile). BM=64, BN=128, BK=32. 128 threads, 4 warps
// 2x2, warp tile 32x64 (af[2] x bf[4] = 8 MMA / 6 frag loads). B staged via
// 3-stage cp.async.cg (raw fp32 -> HW tf32 truncation, CORR in epilogue);
// A staged via register prefetch + rna cvt. One __syncthreads per k-stage.
// smem layout (dynamic, bytes):
//   0:      A bufs  2 x 64x36 floats   (18432)
//   18432:  B bufs  3 x 32x132 floats  (50688)  [aliased as Cs 64x132 in epilogue]
//   69120:  bsm[128], 69632: rp[64] ptr, 70144: atb[64] int  -> total 70400
#define AB_OFF 0
#define BB_OFF 18432
#define SMEM_DYN 70400

template <int K, int NTOT, bool RELU, bool LAYER2>
__global__ __launch_bounds__(128, 3) void moe_gemm_wmma(const float* __restrict__ Xg,
                                                        const float* __restrict__ Wt,
                                                        const float* __restrict__ bias) {
    constexpr int BM = 64, BN = 128, BK = 32, NKC = K / BK;
    constexpr int LDA = 36, LDB = 132, LDC = 132;
    const int pair  = blockIdx.y;
    const int count = d_cnt[pair];
    if (count == 0) return;
    const int n0 = blockIdx.x * BN;

    const float* Xsrc = LAYER2 ? &d_H[0][0] : Xg;
    float*       Out  = LAYER2 ? &d_Y[0][0] : &d_H[0][0];
    const int*   rows = LAYER2 ? d_asg[pair] : d_tok[pair];
    const float* Wp   = Wt + (size_t)pair * K * NTOT + n0;
    const float* bp   = bias + (size_t)pair * NTOT + n0;

    extern __shared__ __align__(16) char smem[];
    float* const Abase = (float*)(smem + AB_OFF);
    float* const Bbase = (float*)(smem + BB_OFF);
    float* const bsm   = (float*)(smem + 69120);
    const float** rp   = (const float**)(smem + 69632);
    int*   atb         = (int*)(smem + 70144);
    const uint32_t sb  = smem_u32(smem);

    const int tid = threadIdx.x;
    const int wid = tid >> 5;
    const int wm  = wid >> 1;     // 0..1 (32-row half)
    const int wn  = wid & 1;      // 0..1 (64-col half)

    bsm[tid] = bp[tid];

    // A staging coords: 4 float4/thread over 64x32 (8 chunks per row)
    int arow[4], akc[4];
#pragma unroll
    for (int i = 0; i < 4; i++) {
        int q = tid + i * 128;
        arow[i] = q >> 3; akc[i] = (q & 7) * 4;
    }

    for (int m0 = 0; m0 < count; m0 += BM) {
        if (tid < BM) {
            int m = m0 + tid;
            rp[tid]  = (m < count) ? (Xsrc + (size_t)rows[m] * K) : (const float*)0;
            atb[tid] = (m < count) ? d_asg[pair][m] : 0;
        }
        __syncthreads();

        const float* myrow[4];
#pragma unroll
        for (int i = 0; i < 4; i++) myrow[i] = rp[arow[i]];

        wmma::fragment<wmma::accumulator, 16, 16, 8, float> acc[2][4];
#pragma unroll
        for (int i = 0; i < 2; i++)
#pragma unroll
            for (int j = 0; j < 4; j++) wmma::fill_fragment(acc[i][j], 0.f);

        // B prologue: issue stages 0,1 via cp.async (8 chunks each)
#pragma unroll
        for (int s = 0; s < 2; s++) {
            uint32_t base = sb + BB_OFF + s * 16896;
            const int k0 = s * BK;
#pragma unroll
            for (int i = 0; i < 8; i++) {
                int q = tid + i * 128;
                int r = q >> 5, c4 = (q & 31) * 4;
                cp16(base + (uint32_t)(r * LDB + c4) * 4, Wp + (size_t)(k0 + r) * NTOT + c4);
            }
            CP_COMMIT();
        }
        // A prefetch stage 0
        float4 pa[4];
#pragma unroll
        for (int i = 0; i < 4; i++) {
            pa[i] = make_float4(0.f, 0.f, 0.f, 0.f);
            if (myrow[i]) pa[i] = *reinterpret_cast<const float4*>(myrow[i] + akc[i]);
        }

        for (int c = 0; c < NKC; c++) {
            // commit A(c) to its double buffer (distinct from buffers in use)
            float* Ac = Abase + (c & 1) * 2304;
#pragma unroll
            for (int i = 0; i < 4; i++) {
                float* a = Ac + arow[i] * LDA + akc[i];
                a[0] = tf32r(pa[i].x); a[1] = tf32r(pa[i].y);
                a[2] = tf32r(pa[i].z); a[3] = tf32r(pa[i].w);
            }
            CP_WAIT1();              // B stage c arrived
            __syncthreads();         // A(c) + B(c) visible to all

            if (c + 2 < NKC) {       // issue B stage c+2
                uint32_t base = sb + BB_OFF + ((c + 2) % 3) * 16896;
                const int k0 = (c + 2) * BK;
#pragma unroll
                for (int i = 0; i < 8; i++) {
                    int q = tid + i * 128;
                    int r = q >> 5, c4 = (q & 31) * 4;
                    cp16(base + (uint32_t)(r * LDB + c4) * 4, Wp + (size_t)(k0 + r) * NTOT + c4);
                }
            }
            CP_COMMIT();
            if (c + 1 < NKC) {       // A prefetch stage c+1
                const int kn = (c + 1) * BK;
#pragma unroll
                for (int i = 0; i < 4; i++) {
                    pa[i] = make_float4(0.f, 0.f, 0.f, 0.f);
                    if (myrow[i]) pa[i] = *reinterpret_cast<const float4*>(myrow[i] + kn + akc[i]);
                }
            }

            const float* Bc = Bbase + (c % 3) * 4224;
#pragma unroll
            for (int kk = 0; kk < BK; kk += 8) {
                wmma::fragment<wmma::matrix_a, 16, 16, 8, wmma::precision::tf32, wmma::row_major> af[2];
                wmma::fragment<wmma::matrix_b, 16, 16, 8, wmma::precision::tf32, wmma::row_major> bf[4];
#pragma unroll
                for (int i = 0; i < 2; i++)
                    wmma::load_matrix_sync(af[i], Ac + (wm * 32 + i * 16) * LDA + kk, LDA);
#pragma unroll
                for (int j = 0; j < 4; j++)
                    wmma::load_matrix_sync(bf[j], Bc + kk * LDB + wn * 64 + j * 16, LDB);
#pragma unroll
                for (int i = 0; i < 2; i++)
#pragma unroll
                    for (int j = 0; j < 4; j++)
                        wmma::mma_sync(acc[i][j], af[i], bf[j], acc[i][j]);
            }
        }

        // epilogue: reuse B pool as Cs
        CP_WAIT0();
        __syncthreads();
        float* const Cs = Bbase;
#pragma unroll
        for (int i = 0; i < 2; i++)
#pragma unroll
            for (int j = 0; j < 4; j++)
                wmma::store_matrix_sync(Cs + (wm * 32 + i * 16) * LDC + wn * 64 + j * 16,
                                        acc[i][j], LDC, wmma::mem_row_major);
        __syncthreads();

#pragma unroll
        for (int it = 0; it < 16; it++) {
            int f = tid + it * 128;           // float4 index over 64x128
            int row = f >> 5;
            int col = (f & 31) * 4;
            int m = m0 + row;
            if (m < count) {
                const float* cr = Cs + row * LDC + col;
                float4 v;
                v.x = cr[0] * CORR + bsm[col + 0];
                v.y = cr[1] * CORR + bsm[col + 1];
                v.z = cr[2] * CORR + bsm[col + 2];
                v.w = cr[3] * CORR + bsm[col + 3];
                if (RELU) {
                    v.x = fmaxf(v.x, 0.f); v.y = fmaxf(v.y, 0.f);
                    v.z = fmaxf(v.z, 0.f); v.w = fmaxf(v.w, 0.f);
                }
                *reinterpret_cast<float4*>(Out + (size_t)atb[row] * NTOT + n0 + col) = v;
            }
        }
        __syncthreads();
    }
}

// ---------------- kernel 4: weighted combine ----------------
__global__ void combine_kernel(float* __restrict__ out) {
    int t = blockIdx.x;
    float w0 = d_w[t * 4 + 0], w1 = d_w[t * 4 + 1];
    float w2 = d_w[t * 4 + 2], w3 = d_w[t * 4 + 3];
    for (int i = threadIdx.x; i < DIM; i += blockDim.x) {
        float s = w0 * d_Y[t * 4 + 0][i] + w1 * d_Y[t * 4 + 1][i]
                + w2 * d_Y[t * 4 + 2][i] + w3 * d_Y[t * 4 + 3][i];
        out[(size_t)t * DIM + i] = s;
    }
}

// ---------------- launch ----------------
extern "C" void kernel_launch(void* const* d_in, const int* in_sizes, int n_in,
                              void* d_out, int out_size) {
    const float* x  = (const float*)d_in[0];
    const float* g1 = (const float*)d_in[1];
    const float* g2 = (const float*)d_in[2];
    const float* W1 = (const float*)d_in[3];
    const float* b1 = (const float*)d_in[4];
    const float* W2 = (const float*)d_in[5];
    const float* b2 = (const float*)d_in[6];
    float* out = (float*)d_out;

    cudaFuncSetAttribute(moe_gemm_wmma<DIM, HDIM, true, false>,
                         cudaFuncAttributeMaxDynamicSharedMemorySize, SMEM_DYN);
    cudaFuncSetAttribute(moe_gemm_wmma<HDIM, DIM, false, true>,
                         cudaFuncAttributeMaxDynamicSharedMemorySize, SMEM_DYN);

    zero_cnt_kernel<<<1, 64>>>();
    route_kernel<<<(TT * 32) / 128, 128>>>(x, g1, g2);
    // layer 1: [count,512] @ [512,1024] + b1, relu  -> d_H
    moe_gemm_wmma<DIM, HDIM, true,  false><<<dim3(HDIM / 128, NPAIR), 128, SMEM_DYN>>>(x, W1, b1);
    // layer 2: [count,1024] @ [1024,512] + b2       -> d_Y
    moe_gemm_wmma<HDIM, DIM, false, true ><<<dim3(DIM / 128, NPAIR), 128, SMEM_DYN>>>(x, W2, b2);
    combine_kernel<<<TT, 128>>>(out);
}